// round 3
// baseline (speedup 1.0000x reference)
#include <cuda_runtime.h>
#include <math.h>
#include <mma.h>
using namespace nvcuda;

#define Bz   64
#define Lz   25
#define Fz   128
#define Pz   10000
#define Cz   400
#define BL   1600
#define PEPAD 10240
#define NBLK 64

// ---------------- device scratch -------------------------------------------------
__device__ __align__(16) float g_buf0[BL * Fz];      // out  (x)
__device__ __align__(16) float g_buf1[BL * Fz];      // outc (xc)
__device__ __align__(16) float g_pe[PEPAD * Fz];
__device__ __align__(16) float g_Wh[2 * 4 * 4 * Fz * Fz];
__device__ __align__(16) float g_Wl[2 * 4 * 4 * Fz * Fz];
__device__ float g_mean[2 * Bz * Lz];                // double-buffered [parity][b][tau]
__device__ unsigned g_maxbits = 0u;
__device__ unsigned g_minbits = 0x7F7FFFFFu;
__device__ unsigned g_gen = 0u;
__device__ unsigned g_cnt = 0u;

// ---------------- embeddings -----------------------------------------------------
__global__ void k_embed(const int* __restrict__ user, const int* __restrict__ poi,
                        const int* __restrict__ cat,  const int* __restrict__ tod,
                        const int* __restrict__ dow,
                        const float* __restrict__ ue,  const float* __restrict__ pe,
                        const float* __restrict__ ce,  const float* __restrict__ te,
                        const float* __restrict__ de,  const float* __restrict__ uec,
                        const float* __restrict__ tec, const float* __restrict__ dec) {
    int r = blockIdx.x, t = threadIdx.x;
    int u = user[r], p = poi[r], c = cat[r], td = tod[r], dw = dow[r];
    g_buf0[r * Fz + t] = ue[u * Fz + t]  + pe[p * Fz + t] + te[td * Fz + t]  + de[dw * Fz + t];
    g_buf1[r * Fz + t] = uec[u * Fz + t] + ce[c * Fz + t] + tec[td * Fz + t] + dec[dw * Fz + t];
}

// ---------------- pad + tf32-round poi_emb ---------------------------------------
__global__ void k_padpe(const float* __restrict__ pe) {
    int r = blockIdx.x, t = threadIdx.x;
    float v = 0.f;
    if (r < Pz) v = wmma::__float_to_tf32(pe[r * Fz + t]);
    g_pe[r * Fz + t] = v;
}

// ---------------- tf32 hi/lo split of all layer weights ---------------------------
__global__ void k_prepw(const float* __restrict__ W) {
    int i = blockIdx.x * 512 + threadIdx.x;   // 1024 blocks x 512 = 524288
    float w = W[i];
    float h = wmma::__float_to_tf32(w);
    g_Wh[i] = h;
    g_Wl[i] = wmma::__float_to_tf32(w - h);
}

// ---------------- min/max over gathered D rows (idempotent) ----------------------
__global__ void k_minmax(const int* __restrict__ poi, const float* __restrict__ Dm) {
    __shared__ float smx[256], smn[256];
    int t = threadIdx.x;
    int row = poi[blockIdx.x];
    const float* rp = Dm + (size_t)row * Pz;
    float mx = -1e30f, mn = 1e30f;
    for (int p = t; p < Pz; p += 256) { float v = rp[p]; mx = fmaxf(mx, v); mn = fminf(mn, v); }
    smx[t] = mx; smn[t] = mn; __syncthreads();
    for (int s = 128; s > 0; s >>= 1) {
        if (t < s) { smx[t] = fmaxf(smx[t], smx[t + s]); smn[t] = fminf(smn[t], smn[t + s]); }
        __syncthreads();
    }
    if (t == 0) {
        atomicMax(&g_maxbits, __float_as_uint(smx[0]));
        atomicMin(&g_minbits, __float_as_uint(smn[0]));
    }
}

// ---------------- grid barrier ----------------------------------------------------
__device__ __forceinline__ void gridbar() {
    __syncthreads();
    if (threadIdx.x == 0) {
        __threadfence();
        volatile unsigned* vg = &g_gen;
        unsigned gen = *vg;
        unsigned prev = atomicAdd(&g_cnt, 1u);
        if (prev == NBLK - 1) {
            g_cnt = 0u;
            __threadfence();
            *vg = gen + 1u;
        } else {
            while (*vg == gen) { }
        }
        __threadfence();
    }
    __syncthreads();
}

// ---------------- tf32x3 GEMM: C(32x128) = A(32x128) @ B^T, B = W(128x128) -------
// 16 warps: 2 row-bands x 8 col-bands of 16.
__device__ __forceinline__ void gemm128(float* __restrict__ C,
                                        const float* __restrict__ Ah, const float* __restrict__ Al,
                                        const float* __restrict__ Bh, const float* __restrict__ Bl) {
    int wid = threadIdx.x >> 5;
    int r0 = (wid >> 3) * 16, o0 = (wid & 7) * 16;
    wmma::fragment<wmma::matrix_a, 16, 16, 8, wmma::precision::tf32, wmma::row_major> fah, fal;
    wmma::fragment<wmma::matrix_b, 16, 16, 8, wmma::precision::tf32, wmma::col_major> fbh, fbl;
    wmma::fragment<wmma::accumulator, 16, 16, 8, float> acc;
    wmma::fill_fragment(acc, 0.f);
    #pragma unroll
    for (int k = 0; k < 128; k += 8) {
        wmma::load_matrix_sync(fah, Ah + r0 * Fz + k, Fz);
        wmma::load_matrix_sync(fal, Al + r0 * Fz + k, Fz);
        wmma::load_matrix_sync(fbh, Bh + o0 * Fz + k, Fz);
        wmma::load_matrix_sync(fbl, Bl + o0 * Fz + k, Fz);
        wmma::mma_sync(acc, fah, fbh, acc);
        wmma::mma_sync(acc, fah, fbl, acc);
        wmma::mma_sync(acc, fal, fbh, acc);
    }
    wmma::store_matrix_sync(C + r0 * Fz + o0, acc, Fz, wmma::mem_row_major);
}

// ---------------- persistent per-batch layer stack --------------------------------
__global__ void __launch_bounds__(512) k_layers(const float* __restrict__ Bv) {
    extern __shared__ float sm[];
    float* oh = sm;                 // out  hi   [32][128]
    float* ol = sm + 4096;          // out  lo
    float* chh = sm + 8192;         // outc hi
    float* cll = sm + 12288;        // outc lo
    float* qh = sm + 16384;         // q hi (also GEMM temp / mirror / proj temp)
    float* ql = sm + 20480;
    float* kh = sm + 24576;
    float* kl = sm + 28672;
    float* vs = sm + 32768;         // v fp32
    float* ah = sm + 36864;         // agg hi
    float* al = sm + 40960;         // agg lo
    float* Ms = sm + 45056;         // 32x32 corr matrix
    __shared__ float s_gms[Lz];
    __shared__ int   s_idx[3];
    __shared__ float s_tc[3];

    const int b = blockIdx.x, t = threadIdx.x;
    const int wid = t >> 5;

    // init: load x/xc -> hi/lo, zero pad rows 25..31 everywhere needed
    for (int i = t; i < 4096; i += 512) {
        int r = i >> 7, d = i & 127;
        float x = 0.f, xc = 0.f;
        if (r < Lz) {
            x  = g_buf0[(b * Lz + r) * Fz + d];
            xc = g_buf1[(b * Lz + r) * Fz + d];
        }
        float xh = wmma::__float_to_tf32(x);
        oh[i] = xh; ol[i] = wmma::__float_to_tf32(x - xh);
        float xch = wmma::__float_to_tf32(xc);
        chh[i] = xch; cll[i] = wmma::__float_to_tf32(xc - xch);
        ah[i] = 0.f; al[i] = 0.f;
    }
    __syncthreads();

    for (int call = 0; call < 8; call++) {
        const int c = call & 3;
        const float *Aih, *Ail, *Kih, *Kil;
        if      (c == 0) { Aih = oh;  Ail = ol;  Kih = oh;  Kil = ol;  }
        else if (c == 1) { Aih = chh; Ail = cll; Kih = chh; Kil = cll; }
        else if (c == 2) { Aih = oh;  Ail = ol;  Kih = chh; Kil = cll; }
        else             { Aih = chh; Ail = cll; Kih = oh;  Kil = ol;  }
        const float* Wh = g_Wh + (size_t)call * 4 * Fz * Fz;
        const float* Wl = g_Wl + (size_t)call * 4 * Fz * Fz;
        const float* bc = Bv + (size_t)call * 4 * Fz;

        // q, k, v projections (tensor)
        gemm128(qh, Aih, Ail, Wh + 0 * Fz * Fz, Wl + 0 * Fz * Fz);
        gemm128(kh, Kih, Kil, Wh + 1 * Fz * Fz, Wl + 1 * Fz * Fz);
        gemm128(vs, Kih, Kil, Wh + 2 * Fz * Fz, Wl + 2 * Fz * Fz);
        __syncthreads();

        // bias add + hi/lo conversion of q,k; bias add of v
        for (int i = t; i < 4096; i += 512) {
            int r = i >> 7, d = i & 127;
            if (r < Lz) {
                float qv = qh[i] + bc[d];
                float h = wmma::__float_to_tf32(qv);
                qh[i] = h; ql[i] = wmma::__float_to_tf32(qv - h);
                float kv = kh[i] + bc[Fz + d];
                h = wmma::__float_to_tf32(kv);
                kh[i] = h; kl[i] = wmma::__float_to_tf32(kv - h);
                vs[i] += bc[2 * Fz + d];
            } else {
                qh[i] = 0.f; ql[i] = 0.f; kh[i] = 0.f; kl[i] = 0.f;
            }
        }
        __syncthreads();

        // M = Q @ K^T  (32x32, K=128) on tensor, warps 0..3
        if (wid < 4) {
            int r0 = (wid >> 1) * 16, o0 = (wid & 1) * 16;
            wmma::fragment<wmma::matrix_a, 16, 16, 8, wmma::precision::tf32, wmma::row_major> fah, fal;
            wmma::fragment<wmma::matrix_b, 16, 16, 8, wmma::precision::tf32, wmma::col_major> fbh, fbl;
            wmma::fragment<wmma::accumulator, 16, 16, 8, float> acc;
            wmma::fill_fragment(acc, 0.f);
            #pragma unroll
            for (int k = 0; k < 128; k += 8) {
                wmma::load_matrix_sync(fah, qh + r0 * Fz + k, Fz);
                wmma::load_matrix_sync(fal, ql + r0 * Fz + k, Fz);
                wmma::load_matrix_sync(fbh, kh + o0 * Fz + k, Fz);
                wmma::load_matrix_sync(fbl, kl + o0 * Fz + k, Fz);
                wmma::mma_sync(acc, fah, fbh, acc);
                wmma::mma_sync(acc, fah, fbl, acc);
                wmma::mma_sync(acc, fal, fbh, acc);
            }
            wmma::store_matrix_sync(Ms + r0 * 32 + o0, acc, 32, wmma::mem_row_major);
        }
        __syncthreads();

        // corr[tau] = sum_n M[(n+tau)%25][n]; write channel-mean to global
        if (t < Lz) {
            float s = 0.f;
            #pragma unroll
            for (int n = 0; n < Lz; n++) {
                int np = n + t; if (np >= Lz) np -= Lz;
                s += Ms[np * 32 + n];
            }
            g_mean[(call & 1) * BL / 1 * 0 + (call & 1) * Bz * Lz + b * Lz + t] = s * (1.0f / Fz);
        }
        gridbar();

        // redundant top-3 + own-batch softmax (mirror in qh)
        float* mm = qh;
        for (int i = t; i < Bz * Lz; i += 512) mm[i] = __ldcg(&g_mean[(call & 1) * Bz * Lz + i]);
        __syncthreads();
        if (t < Lz) {
            float s = 0.f;
            for (int bb = 0; bb < Bz; bb++) s += mm[bb * Lz + t];
            s_gms[t] = s;
        }
        __syncthreads();
        if (t == 0) {
            int id0 = 0, id1 = 0, id2 = 0;
            float v0 = -1e38f, v1 = -1e38f, v2 = -1e38f;
            for (int j = 0; j < Lz; j++) {
                float v = s_gms[j];
                if (v > v0)      { v2 = v1; id2 = id1; v1 = v0; id1 = id0; v0 = v; id0 = j; }
                else if (v > v1) { v2 = v1; id2 = id1; v1 = v; id1 = j; }
                else if (v > v2) { v2 = v; id2 = j; }
            }
            float w0 = mm[b * Lz + id0], w1 = mm[b * Lz + id1], w2 = mm[b * Lz + id2];
            float mx = fmaxf(w0, fmaxf(w1, w2));
            float e0 = expf(w0 - mx), e1 = expf(w1 - mx), e2 = expf(w2 - mx);
            float inv = 1.0f / (e0 + e1 + e2);
            s_tc[0] = e0 * inv; s_tc[1] = e1 * inv; s_tc[2] = e2 * inv;
            s_idx[0] = id0; s_idx[1] = id1; s_idx[2] = id2;
        }
        __syncthreads();

        // lag aggregation -> ag hi/lo
        {
            int i0 = s_idx[0], i1 = s_idx[1], i2 = s_idx[2];
            float c0 = s_tc[0], c1 = s_tc[1], c2 = s_tc[2];
            for (int i = t; i < Lz * Fz; i += 512) {
                int l = i >> 7, d = i & 127;
                int p0 = l + i0; if (p0 >= Lz) p0 -= Lz;
                int p1 = l + i1; if (p1 >= Lz) p1 -= Lz;
                int p2 = l + i2; if (p2 >= Lz) p2 -= Lz;
                float a = c0 * vs[p0 * Fz + d] + c1 * vs[p1 * Fz + d] + c2 * vs[p2 * Fz + d];
                float h = wmma::__float_to_tf32(a);
                ah[l * Fz + d] = h;
                al[l * Fz + d] = wmma::__float_to_tf32(a - h);
            }
        }
        __syncthreads();

        // output projection (qh as C temp)
        gemm128(qh, ah, al, Wh + 3 * Fz * Fz, Wl + 3 * Fz * Fz);
        __syncthreads();

        // convert to destination hi/lo (+bias); pad rows stay zero
        {
            float* dh = (c == 0 || c == 2) ? oh  : chh;
            float* dl = (c == 0 || c == 2) ? ol  : cll;
            const float* b3 = bc + 3 * Fz;
            for (int i = t; i < Lz * Fz; i += 512) {
                int d = i & 127;
                float v = qh[i] + b3[d];
                float h = wmma::__float_to_tf32(v);
                dh[i] = h;
                dl[i] = wmma::__float_to_tf32(v - h);
            }
        }
        __syncthreads();
    }

    // write final out / outc (fp32 = hi + lo)
    for (int i = t; i < Lz * Fz; i += 512) {
        g_buf0[b * Lz * Fz + i] = oh[i] + ol[i];
        g_buf1[b * Lz * Fz + i] = chh[i] + cll[i];
    }
}

// ---------------- final POI scoring: tf32 WMMA + fused exp-gather epilogue -------
__global__ void __launch_bounds__(256) k_final_poi(
        const float* __restrict__ outp, const int* __restrict__ poi,
        const float* __restrict__ Dm,   const float* __restrict__ vw,
        const float* __restrict__ vbp,  float* __restrict__ dst) {
    extern __shared__ float sm[];
    float* a_s = sm;
    float* S   = sm;
    __shared__ int   rows_s[50];
    __shared__ float vws[Lz];

    int t = threadIdx.x, wid = t >> 5;
    int ptile = blockIdx.x, b0 = blockIdx.y * 2;

    for (int i = t; i < 64 * 128; i += 256) {
        int r = i >> 7, d = i & 127;
        int l = r & 31, bb = b0 + (r >> 5);
        float v = 0.f;
        if (l < Lz) v = wmma::__float_to_tf32(outp[((bb * Lz) + l) * Fz + d]);
        a_s[i] = v;
    }
    if (t < 50) rows_s[t] = poi[(b0 + t / Lz) * Lz + (t % Lz)];
    if (t < Lz) vws[t] = vw[t];
    __syncthreads();

    wmma::fragment<wmma::matrix_a, 16, 16, 8, wmma::precision::tf32, wmma::row_major> fa;
    wmma::fragment<wmma::matrix_b, 16, 16, 8, wmma::precision::tf32, wmma::col_major> fb0, fb1;
    wmma::fragment<wmma::accumulator, 16, 16, 8, float> facc[4][2];
    #pragma unroll
    for (int m = 0; m < 4; m++) { wmma::fill_fragment(facc[m][0], 0.f); wmma::fill_fragment(facc[m][1], 0.f); }

    const float* peB = g_pe + (size_t)(ptile * 256) * Fz;
    for (int k = 0; k < 128; k += 8) {
        wmma::load_matrix_sync(fb0, peB + (size_t)((wid * 2 + 0) * 16) * Fz + k, Fz);
        wmma::load_matrix_sync(fb1, peB + (size_t)((wid * 2 + 1) * 16) * Fz + k, Fz);
        #pragma unroll
        for (int m = 0; m < 4; m++) {
            wmma::load_matrix_sync(fa, a_s + (m * 16) * Fz + k, Fz);
            wmma::mma_sync(facc[m][0], fa, fb0, facc[m][0]);
            wmma::mma_sync(facc[m][1], fa, fb1, facc[m][1]);
        }
    }
    __syncthreads();
    #pragma unroll
    for (int m = 0; m < 4; m++) {
        wmma::store_matrix_sync(S + (m * 16) * 264 + (wid * 2 + 0) * 16, facc[m][0], 264, wmma::mem_row_major);
        wmma::store_matrix_sync(S + (m * 16) * 264 + (wid * 2 + 1) * 16, facc[m][1], 264, wmma::mem_row_major);
    }
    __syncthreads();

    int p = ptile * 256 + t;
    if (p < Pz) {
        float neginv = -1.f / (__uint_as_float(g_maxbits) - __uint_as_float(g_minbits));
        float bias = vbp[0];
        #pragma unroll
        for (int bb = 0; bb < 2; bb++) {
            float r = 0.f;
            #pragma unroll
            for (int l = 0; l < Lz; l++) {
                float s = S[(bb * 32 + l) * 264 + t];
                float d = Dm[(size_t)rows_s[bb * Lz + l] * Pz + p];
                r += s * __expf(d * neginv) * vws[l];
            }
            dst[(size_t)(b0 + bb) * Pz + p] = r + bias;
        }
    }
}

// ---------------- final CAT scoring ----------------------------------------------
__global__ void k_final_cat(const float* __restrict__ outcp, const float* __restrict__ ce,
                            const float* __restrict__ vw, const float* __restrict__ vbp,
                            float* __restrict__ dst) {
    __shared__ __align__(16) float y[Fz];
    int b = blockIdx.x, t = threadIdx.x;
    float s = 0.f;
    for (int l = 0; l < Lz; l++) s += vw[l] * outcp[(b * Lz + l) * Fz + t];
    y[t] = s;
    __syncthreads();
    const float4* Y4 = (const float4*)y;
    float bias = vbp[0];
    for (int g = 0; g < 4; g++) {
        int c = g * 128 + t;
        if (c < Cz) {
            const float4* C4 = (const float4*)(ce + c * Fz);
            float acc = 0.f;
            for (int q = 0; q < 32; q++) {
                float4 cv = C4[q], yv = Y4[q];
                acc += cv.x * yv.x + cv.y * yv.y + cv.z * yv.z + cv.w * yv.w;
            }
            dst[b * Cz + c] = acc + bias;
        }
    }
}

// ---------------- host driver ----------------------------------------------------
extern "C" void kernel_launch(void* const* d_in, const int* in_sizes, int n_in,
                              void* d_out, int out_size) {
    const int*   user = (const int*)d_in[0];
    const int*   poi  = (const int*)d_in[1];
    const int*   cat  = (const int*)d_in[2];
    const int*   tod  = (const int*)d_in[5];
    const int*   dow  = (const int*)d_in[6];
    const float* ue   = (const float*)d_in[8];
    const float* pe   = (const float*)d_in[9];
    const float* ce   = (const float*)d_in[10];
    const float* te   = (const float*)d_in[11];
    const float* de   = (const float*)d_in[12];
    const float* uec  = (const float*)d_in[13];
    const float* tec  = (const float*)d_in[14];
    const float* dec  = (const float*)d_in[15];
    const float* W    = (const float*)d_in[16];
    const float* Bvv  = (const float*)d_in[17];
    const float* vw   = (const float*)d_in[18];
    const float* vb   = (const float*)d_in[19];
    const float* Dm   = (const float*)d_in[20];
    float* out = (float*)d_out;

    static int attr_done = 0;
    if (!attr_done) {
        cudaFuncSetAttribute(k_layers,    cudaFuncAttributeMaxDynamicSharedMemorySize, 190 * 1024);
        cudaFuncSetAttribute(k_final_poi, cudaFuncAttributeMaxDynamicSharedMemorySize, 70 * 1024);
        attr_done = 1;
    }

    float *b0p, *b1p;
    cudaGetSymbolAddress((void**)&b0p, g_buf0);
    cudaGetSymbolAddress((void**)&b1p, g_buf1);

    k_embed<<<BL, Fz>>>(user, poi, cat, tod, dow, ue, pe, ce, te, de, uec, tec, dec);
    k_padpe<<<PEPAD, Fz>>>(pe);
    k_prepw<<<1024, 512>>>(W);
    k_minmax<<<BL, 256>>>(poi, Dm);
    k_layers<<<NBLK, 512, 46080 * 4>>>(Bvv);
    k_final_poi<<<dim3(40, 32), 256, 64 * 264 * 4>>>(b0p, poi, Dm, vw, vb, out);
    k_final_cat<<<Bz, 128>>>(b1p, ce, vw, vb, out + (size_t)Bz * Pz);
}

// round 4
// speedup vs baseline: 1.5334x; 1.5334x over previous
#include <cuda_runtime.h>
#include <math.h>
#include <mma.h>
using namespace nvcuda;

#define Bz   64
#define Lz   25
#define Fz   128
#define Pz   10000
#define Cz   400
#define BL   1600
#define PEPAD 10240
#define SLC  (Lz * Fz)          // 3200 floats per (batch, tensor)

// ---------------- device scratch -------------------------------------------------
__device__ __align__(16) float g_st[10][BL * Fz];     // x, xc, out1, outc1, out2, outc2, out3, outc3, out4, outc4
__device__ __align__(16) float g_v8[8][BL * Fz];      // v tensor per call
__device__ float g_mean8[8][Bz * Lz];                 // channel-mean corr per call
__device__ __align__(16) float g_pe[PEPAD * Fz];
__device__ unsigned g_maxbits = 0u;
__device__ unsigned g_minbits = 0x7F7FFFFFu;

// ---------------- embeddings -----------------------------------------------------
__global__ void k_embed(const int* __restrict__ user, const int* __restrict__ poi,
                        const int* __restrict__ cat,  const int* __restrict__ tod,
                        const int* __restrict__ dow,
                        const float* __restrict__ ue,  const float* __restrict__ pe,
                        const float* __restrict__ ce,  const float* __restrict__ te,
                        const float* __restrict__ de,  const float* __restrict__ uec,
                        const float* __restrict__ tec, const float* __restrict__ dec) {
    int r = blockIdx.x, t = threadIdx.x;
    int u = user[r], p = poi[r], c = cat[r], td = tod[r], dw = dow[r];
    g_st[0][r * Fz + t] = ue[u * Fz + t]  + pe[p * Fz + t] + te[td * Fz + t]  + de[dw * Fz + t];
    g_st[1][r * Fz + t] = uec[u * Fz + t] + ce[c * Fz + t] + tec[td * Fz + t] + dec[dw * Fz + t];
}

// ---------------- pad + tf32-round poi_emb ---------------------------------------
__global__ void k_padpe(const float* __restrict__ pe) {
    int r = blockIdx.x, t = threadIdx.x;
    float v = 0.f;
    if (r < Pz) v = wmma::__float_to_tf32(pe[r * Fz + t]);
    g_pe[r * Fz + t] = v;
}

// ---------------- min/max over gathered D rows (idempotent) ----------------------
__global__ void k_minmax(const int* __restrict__ poi, const float* __restrict__ Dm) {
    __shared__ float smx[256], smn[256];
    int t = threadIdx.x;
    int row = poi[blockIdx.x];
    const float4* rp4 = (const float4*)(Dm + (size_t)row * Pz);
    float mx = -1e30f, mn = 1e30f;
    for (int p = t; p < Pz / 4; p += 256) {
        float4 v = __ldg(rp4 + p);
        mx = fmaxf(mx, fmaxf(fmaxf(v.x, v.y), fmaxf(v.z, v.w)));
        mn = fminf(mn, fminf(fminf(v.x, v.y), fminf(v.z, v.w)));
    }
    smx[t] = mx; smn[t] = mn; __syncthreads();
    for (int s = 128; s > 0; s >>= 1) {
        if (t < s) { smx[t] = fmaxf(smx[t], smx[t + s]); smn[t] = fminf(smn[t], smn[t + s]); }
        __syncthreads();
    }
    if (t == 0) {
        atomicMax(&g_maxbits, __float_as_uint(smx[0]));
        atomicMin(&g_minbits, __float_as_uint(smn[0]));
    }
}

// ---------------- core building blocks (256 threads) ------------------------------
// dst[l*128+o] = sum_k a_s[l*128+k]*Wg[o*128+k] + bg[o]   (25 x 128 @ 128x128^T)
__device__ __forceinline__ void proj128(float* __restrict__ dst, const float* __restrict__ a_s,
                                        const float* __restrict__ Wg, const float* __restrict__ bg) {
    const int t = threadIdx.x;
    const int o = t & 127, rg = t >> 7;
    float acc[13];
    #pragma unroll
    for (int r = 0; r < 13; r++) acc[r] = 0.f;
    const float4* W4 = (const float4*)(Wg + o * Fz);
    const float4* A4 = (const float4*)a_s;
    for (int c = 0; c < 32; c++) {
        float4 w = __ldg(W4 + c);
        #pragma unroll
        for (int r = 0; r < 13; r++) {
            int row = rg + 2 * r;
            if (row < Lz) {
                float4 a = A4[row * 32 + c];
                acc[r] += w.x * a.x + w.y * a.y + w.z * a.z + w.w * a.w;
            }
        }
    }
    float bb = __ldg(bg + o);
    #pragma unroll
    for (int r = 0; r < 13; r++) {
        int row = rg + 2 * r;
        if (row < Lz) dst[row * Fz + o] = acc[r] + bb;
    }
}

// channel-mean circular correlation -> meanOut[tau], tau in [0,25)
__device__ __forceinline__ void corr25(const float* __restrict__ q_s, const float* __restrict__ k_s,
                                       float* __restrict__ meanOut) {
    int t = threadIdx.x, w = t >> 5, lane = t & 31;
    for (int tau = w; tau < Lz; tau += 8) {
        float s = 0.f;
        for (int idx = lane; idx < SLC; idx += 32) {
            int n = idx >> 7, d = idx & 127;
            int np = n + tau; if (np >= Lz) np -= Lz;
            s += q_s[np * Fz + d] * k_s[idx];
        }
        #pragma unroll
        for (int o = 16; o > 0; o >>= 1) s += __shfl_down_sync(0xffffffffu, s, o);
        if (lane == 0) meanOut[tau] = s * (1.0f / Fz);
    }
}

// B op: topk + softmax + lag-agg + output projection; result left in out_s and written to dst
__device__ void doB(const float* __restrict__ meanG, const float* __restrict__ vsrc,
                    const float* __restrict__ Wp, const float* __restrict__ bp,
                    float* __restrict__ dstG, float* __restrict__ out_s,
                    float* __restrict__ ag_s, float* __restrict__ mean_s, int b) {
    __shared__ float s_gms[Lz];
    __shared__ int   s_idx[3];
    __shared__ float s_tc[3];
    const int t = threadIdx.x;

    for (int i = t; i < Bz * Lz; i += 256) mean_s[i] = __ldcg(&meanG[i]);
    __syncthreads();
    if (t < Lz) {
        float s = 0.f;
        for (int bb = 0; bb < Bz; bb++) s += mean_s[bb * Lz + t];
        s_gms[t] = s;
    }
    __syncthreads();
    if (t == 0) {
        int id0 = 0, id1 = 0, id2 = 0;
        float v0 = -1e38f, v1 = -1e38f, v2 = -1e38f;
        for (int j = 0; j < Lz; j++) {
            float v = s_gms[j];
            if (v > v0)      { v2 = v1; id2 = id1; v1 = v0; id1 = id0; v0 = v; id0 = j; }
            else if (v > v1) { v2 = v1; id2 = id1; v1 = v; id1 = j; }
            else if (v > v2) { v2 = v; id2 = j; }
        }
        float w0 = mean_s[b * Lz + id0], w1 = mean_s[b * Lz + id1], w2 = mean_s[b * Lz + id2];
        float mx = fmaxf(w0, fmaxf(w1, w2));
        float e0 = expf(w0 - mx), e1 = expf(w1 - mx), e2 = expf(w2 - mx);
        float inv = 1.0f / (e0 + e1 + e2);
        s_tc[0] = e0 * inv; s_tc[1] = e1 * inv; s_tc[2] = e2 * inv;
        s_idx[0] = id0; s_idx[1] = id1; s_idx[2] = id2;
    }
    __syncthreads();
    {
        int i0 = s_idx[0], i1 = s_idx[1], i2 = s_idx[2];
        float c0 = s_tc[0], c1 = s_tc[1], c2 = s_tc[2];
        const float* vb = vsrc + (size_t)b * SLC;
        for (int i = t; i < SLC; i += 256) {
            int l = i >> 7, d = i & 127;
            int p0 = l + i0; if (p0 >= Lz) p0 -= Lz;
            int p1 = l + i1; if (p1 >= Lz) p1 -= Lz;
            int p2 = l + i2; if (p2 >= Lz) p2 -= Lz;
            ag_s[i] = c0 * __ldcg(&vb[p0 * Fz + d]) + c1 * __ldcg(&vb[p1 * Fz + d]) + c2 * __ldcg(&vb[p2 * Fz + d]);
        }
    }
    __syncthreads();
    proj128(out_s, ag_s, Wp, bp);
    __syncthreads();
    float* dst = dstG + (size_t)b * SLC;
    for (int i = t; i < SLC; i += 256) dst[i] = out_s[i];
    __syncthreads();
}

// A op: qkv projections + corr. qbuf/kbuf are smem [25][128] inputs.
__device__ void doA(const float* __restrict__ qbuf, const float* __restrict__ kbuf,
                    const float* __restrict__ Wc, const float* __restrict__ bc,
                    float* __restrict__ vdstG, float* __restrict__ meanDst,
                    float* __restrict__ q_s, float* __restrict__ k_s, float* __restrict__ v_s, int b) {
    const int t = threadIdx.x;
    proj128(q_s, qbuf, Wc,                 bc);
    proj128(k_s, kbuf, Wc + 1 * Fz * Fz,   bc + 1 * Fz);
    proj128(v_s, kbuf, Wc + 2 * Fz * Fz,   bc + 2 * Fz);
    __syncthreads();
    float* vd = vdstG + (size_t)b * SLC;
    for (int i = t; i < SLC; i += 256) vd[i] = v_s[i];
    corr25(q_s, k_s, meanDst + b * Lz);
}

// ---------------- kernel: two independent A ops (grid 64 x 2) --------------------
__global__ void __launch_bounds__(256) k_AA(
        const float* q0, const float* kv0, const float* W0, const float* b0, float* v0, float* m0,
        const float* q1, const float* kv1, const float* W1, const float* b1, float* v1, float* m1) {
    extern __shared__ float sm[];
    float* s0 = sm;            // q src
    float* s1 = sm + SLC;      // kv src
    float* s2 = sm + 2 * SLC;  // q
    float* s3 = sm + 3 * SLC;  // k
    float* s4 = sm + 4 * SLC;  // v
    const int b = blockIdx.x, t = threadIdx.x;
    const int ch = blockIdx.y;
    const float* qg  = ch ? q1  : q0;
    const float* kvg = ch ? kv1 : kv0;
    const float* Wc  = ch ? W1  : W0;
    const float* bc  = ch ? b1  : b0;
    float* vd  = ch ? v1 : v0;
    float* md  = ch ? m1 : m0;

    const float* qsrc = qg + (size_t)b * SLC;
    for (int i = t; i < SLC; i += 256) s0[i] = __ldcg(&qsrc[i]);
    const float* kbuf;
    if (kvg == qg) kbuf = s0;
    else {
        const float* ksrc = kvg + (size_t)b * SLC;
        for (int i = t; i < SLC; i += 256) s1[i] = __ldcg(&ksrc[i]);
        kbuf = s1;
    }
    __syncthreads();
    doA(s0, kbuf, Wc, bc, vd, md, s2, s3, s4, b);
}

// ---------------- kernel: up to 2 B ops + optional A + optional cat --------------
__global__ void __launch_bounds__(256) k_BBA(
        int nB,
        const float* B0_mean, const float* B0_v, const float* B0_W, const float* B0_b, float* B0_dst,
        const float* B1_mean, const float* B1_v, const float* B1_W, const float* B1_b, float* B1_dst,
        int hasA, int aQsel, int aKsel,
        const float* A_qg, const float* A_kg,
        const float* A_W, const float* A_b, float* A_vdst, float* A_mean,
        int hasCat, const float* ce, const float* vw, const float* vbp, float* catdst) {
    extern __shared__ float sm[];
    float* s0 = sm;
    float* s1 = sm + SLC;
    float* s2 = sm + 2 * SLC;
    float* s3 = sm + 3 * SLC;
    float* s4 = sm + 4 * SLC;
    float* s5 = sm + 5 * SLC;   // mean mirror (1600)
    const int b = blockIdx.x, t = threadIdx.x;

    if (nB > 0) doB(B0_mean, B0_v, B0_W, B0_b, B0_dst, s0, s2, s5, b);
    if (nB > 1) doB(B1_mean, B1_v, B1_W, B1_b, B1_dst, s1, s2, s5, b);

    if (hasA) {
        float* qb = aQsel ? s1 : s0;
        float* kb = aKsel ? s1 : s0;
        if (A_qg) {
            const float* src = A_qg + (size_t)b * SLC;
            for (int i = t; i < SLC; i += 256) qb[i] = __ldcg(&src[i]);
        }
        if (A_kg) {
            const float* src = A_kg + (size_t)b * SLC;
            for (int i = t; i < SLC; i += 256) kb[i] = __ldcg(&src[i]);
        }
        __syncthreads();
        doA(qb, kb, A_W, A_b, A_vdst, A_mean, s2, s3, s4, b);
    }

    if (hasCat) {
        __syncthreads();
        if (t < Fz) {
            float s = 0.f;
            for (int l = 0; l < Lz; l++) s += __ldg(&vw[l]) * s0[l * Fz + t];
            s2[t] = s;
        }
        __syncthreads();
        int w = t >> 5, lane = t & 31;
        float bias = __ldg(vbp);
        for (int c = w; c < Cz; c += 8) {
            const float4* C4 = (const float4*)(ce + c * Fz);
            float4 cv = __ldg(&C4[lane]);
            float4 yv = ((const float4*)s2)[lane];
            float s = cv.x * yv.x + cv.y * yv.y + cv.z * yv.z + cv.w * yv.w;
            #pragma unroll
            for (int off = 16; off > 0; off >>= 1) s += __shfl_down_sync(0xffffffffu, s, off);
            if (lane == 0) catdst[b * Cz + c] = s + bias;
        }
    }
}

// ---------------- final POI scoring: tf32 WMMA + fused exp-gather epilogue -------
__global__ void __launch_bounds__(256) k_final_poi(
        const float* __restrict__ outp, const int* __restrict__ poi,
        const float* __restrict__ Dm,   const float* __restrict__ vw,
        const float* __restrict__ vbp,  float* __restrict__ dst) {
    extern __shared__ float sm[];
    float* a_s = sm;
    float* S   = sm;
    __shared__ int   rows_s[50];
    __shared__ float vws[Lz];

    int t = threadIdx.x, wid = t >> 5;
    int ptile = blockIdx.x, b0 = blockIdx.y * 2;

    for (int i = t; i < 64 * 128; i += 256) {
        int r = i >> 7, d = i & 127;
        int l = r & 31, bb = b0 + (r >> 5);
        float v = 0.f;
        if (l < Lz) v = wmma::__float_to_tf32(outp[((bb * Lz) + l) * Fz + d]);
        a_s[i] = v;
    }
    if (t < 50) rows_s[t] = poi[(b0 + t / Lz) * Lz + (t % Lz)];
    if (t < Lz) vws[t] = vw[t];
    __syncthreads();

    wmma::fragment<wmma::matrix_a, 16, 16, 8, wmma::precision::tf32, wmma::row_major> fa;
    wmma::fragment<wmma::matrix_b, 16, 16, 8, wmma::precision::tf32, wmma::col_major> fb0, fb1;
    wmma::fragment<wmma::accumulator, 16, 16, 8, float> facc[4][2];
    #pragma unroll
    for (int m = 0; m < 4; m++) { wmma::fill_fragment(facc[m][0], 0.f); wmma::fill_fragment(facc[m][1], 0.f); }

    const float* peB = g_pe + (size_t)(ptile * 256) * Fz;
    for (int k = 0; k < 128; k += 8) {
        wmma::load_matrix_sync(fb0, peB + (size_t)((wid * 2 + 0) * 16) * Fz + k, Fz);
        wmma::load_matrix_sync(fb1, peB + (size_t)((wid * 2 + 1) * 16) * Fz + k, Fz);
        #pragma unroll
        for (int m = 0; m < 4; m++) {
            wmma::load_matrix_sync(fa, a_s + (m * 16) * Fz + k, Fz);
            wmma::mma_sync(facc[m][0], fa, fb0, facc[m][0]);
            wmma::mma_sync(facc[m][1], fa, fb1, facc[m][1]);
        }
    }
    __syncthreads();
    #pragma unroll
    for (int m = 0; m < 4; m++) {
        wmma::store_matrix_sync(S + (m * 16) * 264 + (wid * 2 + 0) * 16, facc[m][0], 264, wmma::mem_row_major);
        wmma::store_matrix_sync(S + (m * 16) * 264 + (wid * 2 + 1) * 16, facc[m][1], 264, wmma::mem_row_major);
    }
    __syncthreads();

    int p = ptile * 256 + t;
    if (p < Pz) {
        float neginv = -1.f / (__uint_as_float(g_maxbits) - __uint_as_float(g_minbits));
        float bias = vbp[0];
        #pragma unroll
        for (int bb = 0; bb < 2; bb++) {
            float r = 0.f;
            #pragma unroll
            for (int l = 0; l < Lz; l++) {
                float s = S[(bb * 32 + l) * 264 + t];
                float d = Dm[(size_t)rows_s[bb * Lz + l] * Pz + p];
                r += s * __expf(d * neginv) * vws[l];
            }
            dst[(size_t)(b0 + bb) * Pz + p] = r + bias;
        }
    }
}

// ---------------- host driver ----------------------------------------------------
extern "C" void kernel_launch(void* const* d_in, const int* in_sizes, int n_in,
                              void* d_out, int out_size) {
    const int*   user = (const int*)d_in[0];
    const int*   poi  = (const int*)d_in[1];
    const int*   cat  = (const int*)d_in[2];
    const int*   tod  = (const int*)d_in[5];
    const int*   dow  = (const int*)d_in[6];
    const float* ue   = (const float*)d_in[8];
    const float* pe   = (const float*)d_in[9];
    const float* ce   = (const float*)d_in[10];
    const float* te   = (const float*)d_in[11];
    const float* de   = (const float*)d_in[12];
    const float* uec  = (const float*)d_in[13];
    const float* tec  = (const float*)d_in[14];
    const float* dec  = (const float*)d_in[15];
    const float* W    = (const float*)d_in[16];
    const float* Bvv  = (const float*)d_in[17];
    const float* vw   = (const float*)d_in[18];
    const float* vb   = (const float*)d_in[19];
    const float* Dm   = (const float*)d_in[20];
    float* out = (float*)d_out;

    const int LAYER_SMEM = 5 * SLC * 4 + Bz * Lz * 4 + 256;  // 70.9 KB

    static int attr_done = 0;
    if (!attr_done) {
        cudaFuncSetAttribute(k_AA,        cudaFuncAttributeMaxDynamicSharedMemorySize, LAYER_SMEM);
        cudaFuncSetAttribute(k_BBA,       cudaFuncAttributeMaxDynamicSharedMemorySize, LAYER_SMEM);
        cudaFuncSetAttribute(k_final_poi, cudaFuncAttributeMaxDynamicSharedMemorySize, 70 * 1024);
        attr_done = 1;
    }

    float* stp;  cudaGetSymbolAddress((void**)&stp, g_st);
    float* vp;   cudaGetSymbolAddress((void**)&vp,  g_v8);
    float* mp;   cudaGetSymbolAddress((void**)&mp,  g_mean8);
    #define ST(i)  (stp + (size_t)(i) * BL * Fz)
    #define VV(i)  (vp  + (size_t)(i) * BL * Fz)
    #define MM(i)  (mp  + (size_t)(i) * Bz * Lz)
    #define WQKV(call) (W   + (size_t)(call) * 4 * Fz * Fz)
    #define WPRJ(call) (W   + (size_t)(call) * 4 * Fz * Fz + 3 * Fz * Fz)
    #define BQKV(call) (Bvv + (size_t)(call) * 4 * Fz)
    #define BPRJ(call) (Bvv + (size_t)(call) * 4 * Fz + 3 * Fz)

    k_embed<<<BL, Fz>>>(user, poi, cat, tod, dow, ue, pe, ce, te, de, uec, tec, dec);
    k_padpe<<<PEPAD, Fz>>>(pe);
    k_minmax<<<BL, 256>>>(poi, Dm);

    // L1: A(c0: x,x), A(c1: xc,xc)
    k_AA<<<dim3(Bz, 2), 256, LAYER_SMEM>>>(
        ST(0), ST(0), WQKV(0), BQKV(0), VV(0), MM(0),
        ST(1), ST(1), WQKV(1), BQKV(1), VV(1), MM(1));

    // L2: B(c0)->out1(st2), B(c1)->outc1(st3), A(c2: q=out1(s0), kv=outc1(s1))
    k_BBA<<<Bz, 256, LAYER_SMEM>>>(
        2, MM(0), VV(0), WPRJ(0), BPRJ(0), ST(2),
           MM(1), VV(1), WPRJ(1), BPRJ(1), ST(3),
        1, 0, 1, nullptr, nullptr, WQKV(2), BQKV(2), VV(2), MM(2),
        0, nullptr, nullptr, nullptr, nullptr);

    // L3: B(c2)->out2(st4), A(c3: q=outc1(st3 global), kv=out2(s0))
    k_BBA<<<Bz, 256, LAYER_SMEM>>>(
        1, MM(2), VV(2), WPRJ(2), BPRJ(2), ST(4),
           nullptr, nullptr, nullptr, nullptr, nullptr,
        1, 1, 0, ST(3), nullptr, WQKV(3), BQKV(3), VV(3), MM(3),
        0, nullptr, nullptr, nullptr, nullptr);

    // L4b: A(layer2 c0: q=kv=out2(st4))
    k_BBA<<<Bz, 256, LAYER_SMEM>>>(
        0, nullptr, nullptr, nullptr, nullptr, nullptr,
           nullptr, nullptr, nullptr, nullptr, nullptr,
        1, 0, 0, ST(4), nullptr, WQKV(4), BQKV(4), VV(4), MM(4),
        0, nullptr, nullptr, nullptr, nullptr);

    // L4a: B(c3)->outc2(st5), A(layer2 c1: q=kv=outc2(s0))
    k_BBA<<<Bz, 256, LAYER_SMEM>>>(
        1, MM(3), VV(3), WPRJ(3), BPRJ(3), ST(5),
           nullptr, nullptr, nullptr, nullptr, nullptr,
        1, 0, 0, nullptr, nullptr, WQKV(5), BQKV(5), VV(5), MM(5),
        0, nullptr, nullptr, nullptr, nullptr);

    // L5: B(c0_2)->out3(st6), B(c1_2)->outc3(st7), A(c2_2: q=out3(s0), kv=outc3(s1))
    k_BBA<<<Bz, 256, LAYER_SMEM>>>(
        2, MM(4), VV(4), WPRJ(4), BPRJ(4), ST(6),
           MM(5), VV(5), WPRJ(5), BPRJ(5), ST(7),
        1, 0, 1, nullptr, nullptr, WQKV(6), BQKV(6), VV(6), MM(6),
        0, nullptr, nullptr, nullptr, nullptr);

    // L6: B(c2_2)->out4(st8), A(c3_2: q=outc3(st7 global), kv=out4(s0))
    k_BBA<<<Bz, 256, LAYER_SMEM>>>(
        1, MM(6), VV(6), WPRJ(6), BPRJ(6), ST(8),
           nullptr, nullptr, nullptr, nullptr, nullptr,
        1, 1, 0, ST(7), nullptr, WQKV(7), BQKV(7), VV(7), MM(7),
        0, nullptr, nullptr, nullptr, nullptr);

    // L7: B(c3_2)->outc4(st9) + fused final_cat
    k_BBA<<<Bz, 256, LAYER_SMEM>>>(
        1, MM(7), VV(7), WPRJ(7), BPRJ(7), ST(9),
           nullptr, nullptr, nullptr, nullptr, nullptr,
        0, 0, 0, nullptr, nullptr, nullptr, nullptr, nullptr, nullptr,
        1, ce, vw, vb, out + (size_t)Bz * Pz);

    k_final_poi<<<dim3(40, 32), 256, 64 * 264 * 4>>>(ST(8), poi, Dm, vw, vb, out);
}

// round 5
// speedup vs baseline: 1.6109x; 1.0505x over previous
#include <cuda_runtime.h>
#include <math.h>
#include <mma.h>
using namespace nvcuda;

#define Bz   64
#define Lz   25
#define Fz   128
#define Pz   10000
#define Cz   400
#define BL   1600
#define PEPAD 10240
#define SLC  (Lz * Fz)          // 3200

// ---------------- device scratch -------------------------------------------------
__device__ __align__(16) float g_st[10][BL * Fz];   // x, xc, out1..outc4
__device__ __align__(16) float g_v8[8][BL * Fz];    // v per call
__device__ float g_meanH[8][2 * Bz * Lz];           // per call: [half][b][tau] raw sums
__device__ __align__(16) float g_pe[PEPAD * Fz];
__device__ unsigned g_maxbits = 0u;
__device__ unsigned g_minbits = 0x7F7FFFFFu;

// ================= K0: embed + minmax + padpe (mixed grid) ========================
__global__ void __launch_bounds__(256) k_pre(
        const int* __restrict__ user, const int* __restrict__ poi,
        const int* __restrict__ cat,  const int* __restrict__ tod,
        const int* __restrict__ dow,
        const float* __restrict__ ue,  const float* __restrict__ pe,
        const float* __restrict__ ce,  const float* __restrict__ te,
        const float* __restrict__ de,  const float* __restrict__ uec,
        const float* __restrict__ tec, const float* __restrict__ dec,
        const float* __restrict__ Dm) {
    const int bid = blockIdx.x, t = threadIdx.x;
    if (bid < 800) {
        // embed: 2 rows per block
        int r = 2 * bid + (t >> 7);
        int d = t & 127;
        int u = user[r], p = poi[r], c = cat[r], td = tod[r], dw = dow[r];
        g_st[0][r * Fz + d] = ue[u * Fz + d]  + pe[p * Fz + d] + te[td * Fz + d]  + de[dw * Fz + d];
        g_st[1][r * Fz + d] = uec[u * Fz + d] + ce[c * Fz + d] + tec[td * Fz + d] + dec[dw * Fz + d];
    } else if (bid < 2400) {
        // minmax over one gathered D row
        __shared__ float smx[256], smn[256];
        int row = poi[bid - 800];
        const float4* rp4 = (const float4*)(Dm + (size_t)row * Pz);
        float mx = -1e30f, mn = 1e30f;
        for (int p = t; p < Pz / 4; p += 256) {
            float4 v = __ldg(rp4 + p);
            mx = fmaxf(mx, fmaxf(fmaxf(v.x, v.y), fmaxf(v.z, v.w)));
            mn = fminf(mn, fminf(fminf(v.x, v.y), fminf(v.z, v.w)));
        }
        smx[t] = mx; smn[t] = mn; __syncthreads();
        for (int s = 128; s > 0; s >>= 1) {
            if (t < s) { smx[t] = fmaxf(smx[t], smx[t + s]); smn[t] = fminf(smn[t], smn[t + s]); }
            __syncthreads();
        }
        if (t == 0) {
            atomicMax(&g_maxbits, __float_as_uint(smx[0]));
            atomicMin(&g_minbits, __float_as_uint(smn[0]));
        }
    } else {
        // padpe: 20 rows per block
        int p0 = (bid - 2400) * 20;
        for (int it = 0; it < 10; it++) {
            int r = p0 + it * 2 + (t >> 7);
            int d = t & 127;
            float v = 0.f;
            if (r < Pz) v = wmma::__float_to_tf32(pe[r * Fz + d]);
            g_pe[r * Fz + d] = v;
        }
    }
}

// ================= half-projection: dst[25][64] = in[25][128] @ W^T + b ==========
// 512 threads: o = t&63 (local col), rg = t>>6 (0..7); rows rg, rg+8, rg+16, (rg+24 if rg==0)
__device__ __forceinline__ void projH(float* __restrict__ dst, const float* __restrict__ in_full,
                                      const float* __restrict__ Wg, const float* __restrict__ bg,
                                      int half) {
    const int t = threadIdx.x;
    const int o = t & 63, rg = t >> 6;
    const int oc = half * 64 + o;
    float a0 = 0.f, a1 = 0.f, a2 = 0.f, a3 = 0.f;
    const float4* W4 = (const float4*)(Wg + (size_t)oc * Fz);
    const float4* A4 = (const float4*)in_full;
    #pragma unroll 4
    for (int c = 0; c < 32; c++) {
        float4 w = __ldg(W4 + c);
        float4 x;
        x = A4[(rg     ) * 32 + c]; a0 += w.x * x.x + w.y * x.y + w.z * x.z + w.w * x.w;
        x = A4[(rg +  8) * 32 + c]; a1 += w.x * x.x + w.y * x.y + w.z * x.z + w.w * x.w;
        x = A4[(rg + 16) * 32 + c]; a2 += w.x * x.x + w.y * x.y + w.z * x.z + w.w * x.w;
        if (rg == 0) { x = A4[24 * 32 + c]; a3 += w.x * x.x + w.y * x.y + w.z * x.z + w.w * x.w; }
    }
    float bb = __ldg(bg + oc);
    dst[(rg     ) * 64 + o] = a0 + bb;
    dst[(rg +  8) * 64 + o] = a1 + bb;
    dst[(rg + 16) * 64 + o] = a2 + bb;
    if (rg == 0) dst[24 * 64 + o] = a3 + bb;
}

// ================= A op: qkv (half cols) + partial corr ===========================
__device__ void doA(const float* __restrict__ inq, const float* __restrict__ inkv,
                    const float* __restrict__ Wc, const float* __restrict__ bc,
                    float* __restrict__ vdstG, float* __restrict__ meanH,
                    float* __restrict__ qh, float* __restrict__ kh, float* __restrict__ vh,
                    int b, int half) {
    const int t = threadIdx.x;
    projH(qh, inq,  Wc,               bc,           half);
    projH(kh, inkv, Wc + 1 * Fz * Fz, bc + 1 * Fz,  half);
    projH(vh, inkv, Wc + 2 * Fz * Fz, bc + 2 * Fz,  half);
    __syncthreads();
    // store v half to global
    float* vd = vdstG + (size_t)b * SLC;
    for (int i = t; i < Lz * 64; i += 512) {
        int l = i >> 6, d = i & 63;
        vd[l * Fz + half * 64 + d] = vh[i];
    }
    // partial circular correlation over own 64 dims
    const float4* q4 = (const float4*)qh;
    const float4* k4 = (const float4*)kh;
    int w = t >> 5, lane = t & 31;
    for (int tau = w; tau < Lz; tau += 16) {
        float s = 0.f;
        for (int idx = lane; idx < Lz * 16; idx += 32) {
            int n = idx >> 4, d4 = idx & 15;
            int np = n + tau; if (np >= Lz) np -= Lz;
            float4 a = q4[np * 16 + d4];
            float4 bb = k4[idx];
            s += a.x * bb.x + a.y * bb.y + a.z * bb.z + a.w * bb.w;
        }
        #pragma unroll
        for (int off = 16; off > 0; off >>= 1) s += __shfl_down_sync(0xffffffffu, s, off);
        if (lane == 0) meanH[half * Bz * Lz + b * Lz + tau] = s;
    }
}

// ================= A kernel (1 or 2 ops, 128 blocks each) =========================
__global__ void __launch_bounds__(512) k_A(
        const float* q0, const float* kv0, const float* W0, const float* b0, float* v0, float* m0,
        const float* q1, const float* kv1, const float* W1, const float* b1, float* v1, float* m1) {
    extern __shared__ float sm[];
    float* inq  = sm;           // 3200
    float* inkv = sm + SLC;     // 3200
    float* qh   = sm + 2*SLC;            // 1600
    float* kh   = sm + 2*SLC + 1600;     // 1600
    float* vh   = sm + 2*SLC + 3200;     // 1600
    const int idx = blockIdx.x, t = threadIdx.x;
    const int op = idx >> 7, b = (idx & 127) >> 1, half = idx & 1;
    const float* qg  = op ? q1  : q0;
    const float* kvg = op ? kv1 : kv0;
    const float* Wc  = op ? W1  : W0;
    const float* bc  = op ? b1  : b0;
    float* vd = op ? v1 : v0;
    float* md = op ? m1 : m0;

    const float4* qs = (const float4*)(qg + (size_t)b * SLC);
    for (int i = t; i < SLC / 4; i += 512) ((float4*)inq)[i] = qs[i];
    const float* kbuf = inq;
    if (kvg != qg) {
        const float4* ks = (const float4*)(kvg + (size_t)b * SLC);
        for (int i = t; i < SLC / 4; i += 512) ((float4*)inkv)[i] = ks[i];
        kbuf = inkv;
    }
    __syncthreads();
    doA(inq, kbuf, Wc, bc, vd, md, qh, kh, vh, b, half);
}

// ================= B op: topk + softmax + agg + half out-proj =====================
__device__ void doB(const float* __restrict__ meanH, const float* __restrict__ vsrc,
                    const float* __restrict__ Wp, const float* __restrict__ bp,
                    float* __restrict__ dstG,
                    float* __restrict__ ms, float* __restrict__ ag, float* __restrict__ outh,
                    int b, int half) {
    __shared__ float s_gms[Lz];
    __shared__ int   s_idx[3];
    __shared__ float s_tc[3];
    const int t = threadIdx.x;
    for (int i = t; i < Bz * Lz; i += 512)
        ms[i] = (meanH[i] + meanH[Bz * Lz + i]) * (1.0f / Fz);
    __syncthreads();
    if (t < Lz) {
        float s = 0.f;
        for (int bb = 0; bb < Bz; bb++) s += ms[bb * Lz + t];
        s_gms[t] = s;
    }
    __syncthreads();
    if (t == 0) {
        int id0 = 0, id1 = 0, id2 = 0;
        float v0 = -1e38f, v1 = -1e38f, v2 = -1e38f;
        for (int j = 0; j < Lz; j++) {
            float v = s_gms[j];
            if (v > v0)      { v2 = v1; id2 = id1; v1 = v0; id1 = id0; v0 = v; id0 = j; }
            else if (v > v1) { v2 = v1; id2 = id1; v1 = v; id1 = j; }
            else if (v > v2) { v2 = v; id2 = j; }
        }
        float w0 = ms[b * Lz + id0], w1 = ms[b * Lz + id1], w2 = ms[b * Lz + id2];
        float mx = fmaxf(w0, fmaxf(w1, w2));
        float e0 = expf(w0 - mx), e1 = expf(w1 - mx), e2 = expf(w2 - mx);
        float inv = 1.0f / (e0 + e1 + e2);
        s_tc[0] = e0 * inv; s_tc[1] = e1 * inv; s_tc[2] = e2 * inv;
        s_idx[0] = id0; s_idx[1] = id1; s_idx[2] = id2;
    }
    __syncthreads();
    {
        int i0 = s_idx[0], i1 = s_idx[1], i2 = s_idx[2];
        float c0 = s_tc[0], c1 = s_tc[1], c2 = s_tc[2];
        const float* vb = vsrc + (size_t)b * SLC;
        for (int i = t; i < SLC; i += 512) {
            int l = i >> 7, d = i & 127;
            int p0 = l + i0; if (p0 >= Lz) p0 -= Lz;
            int p1 = l + i1; if (p1 >= Lz) p1 -= Lz;
            int p2 = l + i2; if (p2 >= Lz) p2 -= Lz;
            ag[i] = c0 * vb[p0 * Fz + d] + c1 * vb[p1 * Fz + d] + c2 * vb[p2 * Fz + d];
        }
    }
    __syncthreads();
    projH(outh, ag, Wp, bp, half);
    __syncthreads();
    float* dst = dstG + (size_t)b * SLC;
    for (int i = t; i < Lz * 64; i += 512) {
        int l = i >> 6, d = i & 63;
        dst[l * Fz + half * 64 + d] = outh[i];
    }
}

// ================= B kernel (1 or 2 ops, 128 blocks each) =========================
__global__ void __launch_bounds__(512) k_B(
        const float* m0, const float* v0, const float* W0, const float* b0, float* d0,
        const float* m1, const float* v1, const float* W1, const float* b1, float* d1) {
    extern __shared__ float sm[];
    float* ms   = sm;                  // 1600
    float* ag   = sm + 1600;           // 3200
    float* outh = sm + 4800;           // 1600
    const int idx = blockIdx.x;
    const int op = idx >> 7, b = (idx & 127) >> 1, half = idx & 1;
    const float* mh = op ? m1 : m0;
    const float* vs = op ? v1 : v0;
    const float* Wp = op ? W1 : W0;
    const float* bp = op ? b1 : b0;
    float* dst = op ? d1 : d0;
    doB(mh, vs, Wp, bp, dst, ms, ag, outh, b, half);
}

// ================= final: POI (tf32 WMMA, fused exp-gather) + CAT =================
__global__ void __launch_bounds__(256) k_final(
        const float* __restrict__ outp, const float* __restrict__ outcp,
        const int* __restrict__ poi,  const float* __restrict__ Dm,
        const float* __restrict__ ce, const float* __restrict__ vw,
        const float* __restrict__ vbp, float* __restrict__ dst_poi,
        float* __restrict__ dst_cat) {
    extern __shared__ float sm[];
    const int bid = blockIdx.x, t = threadIdx.x;

    if (bid < 1280) {
        float* a_s = sm;
        float* S   = sm;
        __shared__ int   rows_s[50];
        __shared__ float vws[Lz];
        int wid = t >> 5;
        int ptile = bid % 40, b0 = (bid / 40) * 2;

        for (int i = t; i < 64 * 128; i += 256) {
            int r = i >> 7, d = i & 127;
            int l = r & 31, bb = b0 + (r >> 5);
            float v = 0.f;
            if (l < Lz) v = wmma::__float_to_tf32(outp[((bb * Lz) + l) * Fz + d]);
            a_s[i] = v;
        }
        if (t < 50) rows_s[t] = poi[(b0 + t / Lz) * Lz + (t % Lz)];
        if (t < Lz) vws[t] = vw[t];
        __syncthreads();

        wmma::fragment<wmma::matrix_a, 16, 16, 8, wmma::precision::tf32, wmma::row_major> fa;
        wmma::fragment<wmma::matrix_b, 16, 16, 8, wmma::precision::tf32, wmma::col_major> fb0, fb1;
        wmma::fragment<wmma::accumulator, 16, 16, 8, float> facc[4][2];
        #pragma unroll
        for (int m = 0; m < 4; m++) { wmma::fill_fragment(facc[m][0], 0.f); wmma::fill_fragment(facc[m][1], 0.f); }

        const float* peB = g_pe + (size_t)(ptile * 256) * Fz;
        for (int k = 0; k < 128; k += 8) {
            wmma::load_matrix_sync(fb0, peB + (size_t)((wid * 2 + 0) * 16) * Fz + k, Fz);
            wmma::load_matrix_sync(fb1, peB + (size_t)((wid * 2 + 1) * 16) * Fz + k, Fz);
            #pragma unroll
            for (int m = 0; m < 4; m++) {
                wmma::load_matrix_sync(fa, a_s + (m * 16) * Fz + k, Fz);
                wmma::mma_sync(facc[m][0], fa, fb0, facc[m][0]);
                wmma::mma_sync(facc[m][1], fa, fb1, facc[m][1]);
            }
        }
        __syncthreads();
        #pragma unroll
        for (int m = 0; m < 4; m++) {
            wmma::store_matrix_sync(S + (m * 16) * 264 + (wid * 2 + 0) * 16, facc[m][0], 264, wmma::mem_row_major);
            wmma::store_matrix_sync(S + (m * 16) * 264 + (wid * 2 + 1) * 16, facc[m][1], 264, wmma::mem_row_major);
        }
        __syncthreads();

        int p = ptile * 256 + t;
        if (p < Pz) {
            float neginv = -1.f / (__uint_as_float(g_maxbits) - __uint_as_float(g_minbits));
            float bias = vbp[0];
            #pragma unroll
            for (int bb = 0; bb < 2; bb++) {
                float r = 0.f;
                #pragma unroll
                for (int l = 0; l < Lz; l++) {
                    float s = S[(bb * 32 + l) * 264 + t];
                    float d = Dm[(size_t)rows_s[bb * Lz + l] * Pz + p];
                    r += s * __expf(d * neginv) * vws[l];
                }
                dst_poi[(size_t)(b0 + bb) * Pz + p] = r + bias;
            }
        }
    } else {
        // CAT: one block per batch
        int b = bid - 1280;
        float* y = sm;   // 128
        if (t < Fz) {
            float s = 0.f;
            for (int l = 0; l < Lz; l++) s += __ldg(&vw[l]) * outcp[(size_t)b * SLC + l * Fz + t];
            y[t] = s;
        }
        __syncthreads();
        int w = t >> 5, lane = t & 31;
        float bias = __ldg(vbp);
        const float4* Y4 = (const float4*)y;
        float4 yv = Y4[lane];
        for (int c = w; c < Cz; c += 8) {
            const float4* C4 = (const float4*)(ce + (size_t)c * Fz);
            float4 cv = __ldg(&C4[lane]);
            float s = cv.x * yv.x + cv.y * yv.y + cv.z * yv.z + cv.w * yv.w;
            #pragma unroll
            for (int off = 16; off > 0; off >>= 1) s += __shfl_down_sync(0xffffffffu, s, off);
            if (lane == 0) dst_cat[b * Cz + c] = s + bias;
        }
    }
}

// ---------------- host driver ----------------------------------------------------
extern "C" void kernel_launch(void* const* d_in, const int* in_sizes, int n_in,
                              void* d_out, int out_size) {
    const int*   user = (const int*)d_in[0];
    const int*   poi  = (const int*)d_in[1];
    const int*   cat  = (const int*)d_in[2];
    const int*   tod  = (const int*)d_in[5];
    const int*   dow  = (const int*)d_in[6];
    const float* ue   = (const float*)d_in[8];
    const float* pe   = (const float*)d_in[9];
    const float* ce   = (const float*)d_in[10];
    const float* te   = (const float*)d_in[11];
    const float* de   = (const float*)d_in[12];
    const float* uec  = (const float*)d_in[13];
    const float* tec  = (const float*)d_in[14];
    const float* dec  = (const float*)d_in[15];
    const float* W    = (const float*)d_in[16];
    const float* Bvv  = (const float*)d_in[17];
    const float* vw   = (const float*)d_in[18];
    const float* vb   = (const float*)d_in[19];
    const float* Dm   = (const float*)d_in[20];
    float* out = (float*)d_out;

    const int ASM = (2 * SLC + 3 * Lz * 64) * 4;          // 44800 B
    const int BSM = (Bz * Lz + SLC + Lz * 64) * 4;        // 25600 B
    const int FSM = 64 * 264 * 4;                          // 67584 B

    static int attr_done = 0;
    if (!attr_done) {
        cudaFuncSetAttribute(k_A,     cudaFuncAttributeMaxDynamicSharedMemorySize, ASM);
        cudaFuncSetAttribute(k_B,     cudaFuncAttributeMaxDynamicSharedMemorySize, BSM);
        cudaFuncSetAttribute(k_final, cudaFuncAttributeMaxDynamicSharedMemorySize, FSM);
        attr_done = 1;
    }

    float* stp;  cudaGetSymbolAddress((void**)&stp, g_st);
    float* vp;   cudaGetSymbolAddress((void**)&vp,  g_v8);
    float* mp;   cudaGetSymbolAddress((void**)&mp,  g_meanH);
    #define ST(i)  (stp + (size_t)(i) * BL * Fz)
    #define VV(i)  (vp  + (size_t)(i) * BL * Fz)
    #define MM(i)  (mp  + (size_t)(i) * 2 * Bz * Lz)
    #define WQKV(c) (W   + (size_t)(c) * 4 * Fz * Fz)
    #define WPRJ(c) (W   + (size_t)(c) * 4 * Fz * Fz + 3 * Fz * Fz)
    #define BQKV(c) (Bvv + (size_t)(c) * 4 * Fz)
    #define BPRJ(c) (Bvv + (size_t)(c) * 4 * Fz + 3 * Fz)

    // K0: embed + minmax + padpe
    k_pre<<<2912, 256>>>(user, poi, cat, tod, dow, ue, pe, ce, te, de, uec, tec, dec, Dm);

    // c0: AC(x,x) ; c1: AC(xc,xc)
    k_A<<<256, 512, ASM>>>(ST(0), ST(0), WQKV(0), BQKV(0), VV(0), MM(0),
                           ST(1), ST(1), WQKV(1), BQKV(1), VV(1), MM(1));
    k_B<<<256, 512, BSM>>>(MM(0), VV(0), WPRJ(0), BPRJ(0), ST(2),
                           MM(1), VV(1), WPRJ(1), BPRJ(1), ST(3));
    // c2: AC(out1, outc1)
    k_A<<<128, 512, ASM>>>(ST(2), ST(3), WQKV(2), BQKV(2), VV(2), MM(2),
                           nullptr, nullptr, nullptr, nullptr, nullptr, nullptr);
    k_B<<<128, 512, BSM>>>(MM(2), VV(2), WPRJ(2), BPRJ(2), ST(4),
                           nullptr, nullptr, nullptr, nullptr, nullptr);
    // c3: AC(outc1, out2) ; c4 (=L2 c0): AC(out2, out2)
    k_A<<<256, 512, ASM>>>(ST(3), ST(4), WQKV(3), BQKV(3), VV(3), MM(3),
                           ST(4), ST(4), WQKV(4), BQKV(4), VV(4), MM(4));
    k_B<<<256, 512, BSM>>>(MM(3), VV(3), WPRJ(3), BPRJ(3), ST(5),
                           MM(4), VV(4), WPRJ(4), BPRJ(4), ST(6));
    // c5: AC(outc2, outc2)
    k_A<<<128, 512, ASM>>>(ST(5), ST(5), WQKV(5), BQKV(5), VV(5), MM(5),
                           nullptr, nullptr, nullptr, nullptr, nullptr, nullptr);
    k_B<<<128, 512, BSM>>>(MM(5), VV(5), WPRJ(5), BPRJ(5), ST(7),
                           nullptr, nullptr, nullptr, nullptr, nullptr);
    // c6: AC(out3, outc3)
    k_A<<<128, 512, ASM>>>(ST(6), ST(7), WQKV(6), BQKV(6), VV(6), MM(6),
                           nullptr, nullptr, nullptr, nullptr, nullptr, nullptr);
    k_B<<<128, 512, BSM>>>(MM(6), VV(6), WPRJ(6), BPRJ(6), ST(8),
                           nullptr, nullptr, nullptr, nullptr, nullptr);
    // c7: AC(outc3, out4)
    k_A<<<128, 512, ASM>>>(ST(7), ST(8), WQKV(7), BQKV(7), VV(7), MM(7),
                           nullptr, nullptr, nullptr, nullptr, nullptr, nullptr);
    k_B<<<128, 512, BSM>>>(MM(7), VV(7), WPRJ(7), BPRJ(7), ST(9),
                           nullptr, nullptr, nullptr, nullptr, nullptr);

    // final: POI (1280 blocks) + CAT (64 blocks)
    k_final<<<1344, 256, FSM>>>(ST(8), ST(9), poi, Dm, ce, vw, vb,
                                out, out + (size_t)Bz * Pz);
}

// round 6
// speedup vs baseline: 2.5824x; 1.6031x over previous
#include <cuda_runtime.h>
#include <math.h>
#include <mma.h>
using namespace nvcuda;

#define Bz   64
#define Lz   25
#define Fz   128
#define Pz   10000
#define Cz   400
#define BL   1600
#define PEPAD 10240
#define SLC  (Lz * Fz)          // 3200
#define WPAD 132                // padded row stride for W tile in smem (floats)
#define WTS  (64 * WPAD)        // 8448 floats

// ---------------- device scratch -------------------------------------------------
__device__ __align__(16) float g_st[10][BL * Fz];   // x, xc, out1..outc4
__device__ __align__(16) float g_v8[8][BL * Fz];    // v per call
__device__ float g_meanH[8][2 * Bz * Lz];           // per call: [half][b][tau] raw sums
__device__ __align__(16) float g_pe[PEPAD * Fz];
__device__ unsigned g_maxbits = 0u;
__device__ unsigned g_minbits = 0x7F7FFFFFu;

// ================= K0: embed + minmax + padpe (mixed grid) ========================
__global__ void __launch_bounds__(256) k_pre(
        const int* __restrict__ user, const int* __restrict__ poi,
        const int* __restrict__ cat,  const int* __restrict__ tod,
        const int* __restrict__ dow,
        const float* __restrict__ ue,  const float* __restrict__ pe,
        const float* __restrict__ ce,  const float* __restrict__ te,
        const float* __restrict__ de,  const float* __restrict__ uec,
        const float* __restrict__ tec, const float* __restrict__ dec,
        const float* __restrict__ Dm) {
    const int bid = blockIdx.x, t = threadIdx.x;
    if (bid < 800) {
        int r = 2 * bid + (t >> 7);
        int d = t & 127;
        int u = user[r], p = poi[r], c = cat[r], td = tod[r], dw = dow[r];
        g_st[0][r * Fz + d] = ue[u * Fz + d]  + pe[p * Fz + d] + te[td * Fz + d]  + de[dw * Fz + d];
        g_st[1][r * Fz + d] = uec[u * Fz + d] + ce[c * Fz + d] + tec[td * Fz + d] + dec[dw * Fz + d];
    } else if (bid < 2400) {
        __shared__ float smx[256], smn[256];
        int row = poi[bid - 800];
        const float4* rp4 = (const float4*)(Dm + (size_t)row * Pz);
        float mx = -1e30f, mn = 1e30f;
        for (int p = t; p < Pz / 4; p += 256) {
            float4 v = __ldg(rp4 + p);
            mx = fmaxf(mx, fmaxf(fmaxf(v.x, v.y), fmaxf(v.z, v.w)));
            mn = fminf(mn, fminf(fminf(v.x, v.y), fminf(v.z, v.w)));
        }
        smx[t] = mx; smn[t] = mn; __syncthreads();
        for (int s = 128; s > 0; s >>= 1) {
            if (t < s) { smx[t] = fmaxf(smx[t], smx[t + s]); smn[t] = fminf(smn[t], smn[t + s]); }
            __syncthreads();
        }
        if (t == 0) {
            atomicMax(&g_maxbits, __float_as_uint(smx[0]));
            atomicMin(&g_minbits, __float_as_uint(smn[0]));
        }
    } else {
        int p0 = (bid - 2400) * 20;
        for (int it = 0; it < 10; it++) {
            int r = p0 + it * 2 + (t >> 7);
            int d = t & 127;
            float v = 0.f;
            if (r < Pz) v = wmma::__float_to_tf32(pe[r * Fz + d]);
            g_pe[r * Fz + d] = v;
        }
    }
}

// ======== stage 64x128 W half-tile into smem (coalesced), pad rows to 132 ========
__device__ __forceinline__ void stageW(float* __restrict__ Ws, const float* __restrict__ Wg,
                                       int half) {
    const int t = threadIdx.x;
    const float4* src = (const float4*)(Wg + (size_t)(half * 64) * Fz);
    #pragma unroll
    for (int i = t; i < 64 * 32; i += 512) {
        int row = i >> 5, c = i & 31;
        float4 w = __ldg(src + row * 32 + c);
        *(float4*)&Ws[row * WPAD + c * 4] = w;
    }
}

// ===== half-projection from smem W: dst[25][64] = in[25][128] @ Ws^T + b =========
// 512 threads: o = t&63, rg = t>>6 (0..7); rows rg, rg+8, rg+16, (24 if rg==0)
__device__ __forceinline__ void projH(float* __restrict__ dst, const float* __restrict__ in_full,
                                      const float* __restrict__ Ws, const float* __restrict__ bg,
                                      int half) {
    const int t = threadIdx.x;
    const int o = t & 63, rg = t >> 6;
    float a0 = 0.f, a1 = 0.f, a2 = 0.f, a3 = 0.f;
    const float4* W4 = (const float4*)(Ws + o * WPAD);
    const float4* A4 = (const float4*)in_full;
    #pragma unroll 8
    for (int c = 0; c < 32; c++) {
        float4 w = W4[c];
        float4 x;
        x = A4[(rg     ) * 32 + c]; a0 += w.x * x.x + w.y * x.y + w.z * x.z + w.w * x.w;
        x = A4[(rg +  8) * 32 + c]; a1 += w.x * x.x + w.y * x.y + w.z * x.z + w.w * x.w;
        x = A4[(rg + 16) * 32 + c]; a2 += w.x * x.x + w.y * x.y + w.z * x.z + w.w * x.w;
        if (rg == 0) { x = A4[24 * 32 + c]; a3 += w.x * x.x + w.y * x.y + w.z * x.z + w.w * x.w; }
    }
    float bb = __ldg(bg + half * 64 + o);
    dst[(rg     ) * 64 + o] = a0 + bb;
    dst[(rg +  8) * 64 + o] = a1 + bb;
    dst[(rg + 16) * 64 + o] = a2 + bb;
    if (rg == 0) dst[24 * 64 + o] = a3 + bb;
}

// ================= A op: qkv (half cols) + partial corr ===========================
__device__ void doA(const float* __restrict__ inq, const float* __restrict__ inkv,
                    const float* __restrict__ Wc, const float* __restrict__ bc,
                    float* __restrict__ vdstG, float* __restrict__ meanH,
                    float* __restrict__ qh, float* __restrict__ kh, float* __restrict__ vh,
                    float* __restrict__ Ws, int b, int half) {
    const int t = threadIdx.x;
    stageW(Ws, Wc, half);                       __syncthreads();
    projH(qh, inq,  Ws, bc,          half);     __syncthreads();
    stageW(Ws, Wc + 1 * Fz * Fz, half);         __syncthreads();
    projH(kh, inkv, Ws, bc + 1 * Fz, half);     __syncthreads();
    stageW(Ws, Wc + 2 * Fz * Fz, half);         __syncthreads();
    projH(vh, inkv, Ws, bc + 2 * Fz, half);     __syncthreads();

    // store v half to global
    float* vd = vdstG + (size_t)b * SLC;
    for (int i = t; i < Lz * 64; i += 512) {
        int l = i >> 6, d = i & 63;
        vd[l * Fz + half * 64 + d] = vh[i];
    }
    // partial circular correlation over own 64 dims
    const float4* q4 = (const float4*)qh;
    const float4* k4 = (const float4*)kh;
    int w = t >> 5, lane = t & 31;
    for (int tau = w; tau < Lz; tau += 16) {
        float s = 0.f;
        for (int idx = lane; idx < Lz * 16; idx += 32) {
            int n = idx >> 4, d4 = idx & 15;
            int np = n + tau; if (np >= Lz) np -= Lz;
            float4 a = q4[np * 16 + d4];
            float4 bb = k4[idx];
            s += a.x * bb.x + a.y * bb.y + a.z * bb.z + a.w * bb.w;
        }
        #pragma unroll
        for (int off = 16; off > 0; off >>= 1) s += __shfl_down_sync(0xffffffffu, s, off);
        if (lane == 0) meanH[half * Bz * Lz + b * Lz + tau] = s;
    }
}

// ================= A kernel (1 or 2 ops, 128 blocks each) =========================
__global__ void __launch_bounds__(512) k_A(
        const float* q0, const float* kv0, const float* W0, const float* b0, float* v0, float* m0,
        const float* q1, const float* kv1, const float* W1, const float* b1, float* v1, float* m1) {
    extern __shared__ float sm[];
    float* inq  = sm;                       // 3200
    float* inkv = sm + SLC;                 // 3200
    float* qh   = sm + 2*SLC;               // 1600
    float* kh   = sm + 2*SLC + 1600;        // 1600
    float* vh   = sm + 2*SLC + 3200;        // 1600
    float* Ws   = sm + 2*SLC + 4800;        // 8448
    const int idx = blockIdx.x, t = threadIdx.x;
    const int op = idx >> 7, b = (idx & 127) >> 1, half = idx & 1;
    const float* qg  = op ? q1  : q0;
    const float* kvg = op ? kv1 : kv0;
    const float* Wc  = op ? W1  : W0;
    const float* bc  = op ? b1  : b0;
    float* vd = op ? v1 : v0;
    float* md = op ? m1 : m0;

    const float4* qs = (const float4*)(qg + (size_t)b * SLC);
    for (int i = t; i < SLC / 4; i += 512) ((float4*)inq)[i] = qs[i];
    const float* kbuf = inq;
    if (kvg != qg) {
        const float4* ks = (const float4*)(kvg + (size_t)b * SLC);
        for (int i = t; i < SLC / 4; i += 512) ((float4*)inkv)[i] = ks[i];
        kbuf = inkv;
    }
    __syncthreads();
    doA(inq, kbuf, Wc, bc, vd, md, qh, kh, vh, Ws, b, half);
}

// ================= B op: topk + softmax + agg + half out-proj =====================
__device__ void doB(const float* __restrict__ meanH, const float* __restrict__ vsrc,
                    const float* __restrict__ Wp, const float* __restrict__ bp,
                    float* __restrict__ dstG,
                    float* __restrict__ ms, float* __restrict__ ag, float* __restrict__ outh,
                    float* __restrict__ Ws, int b, int half) {
    __shared__ float s_gms[Lz];
    __shared__ int   s_idx[3];
    __shared__ float s_tc[3];
    const int t = threadIdx.x;
    stageW(Ws, Wp, half);   // overlap W staging with mean processing
    for (int i = t; i < Bz * Lz; i += 512)
        ms[i] = (meanH[i] + meanH[Bz * Lz + i]) * (1.0f / Fz);
    __syncthreads();
    if (t < Lz) {
        float s = 0.f;
        for (int bb = 0; bb < Bz; bb++) s += ms[bb * Lz + t];
        s_gms[t] = s;
    }
    __syncthreads();
    if (t == 0) {
        int id0 = 0, id1 = 0, id2 = 0;
        float v0 = -1e38f, v1 = -1e38f, v2 = -1e38f;
        for (int j = 0; j < Lz; j++) {
            float v = s_gms[j];
            if (v > v0)      { v2 = v1; id2 = id1; v1 = v0; id1 = id0; v0 = v; id0 = j; }
            else if (v > v1) { v2 = v1; id2 = id1; v1 = v; id1 = j; }
            else if (v > v2) { v2 = v; id2 = j; }
        }
        float w0 = ms[b * Lz + id0], w1 = ms[b * Lz + id1], w2 = ms[b * Lz + id2];
        float mx = fmaxf(w0, fmaxf(w1, w2));
        float e0 = expf(w0 - mx), e1 = expf(w1 - mx), e2 = expf(w2 - mx);
        float inv = 1.0f / (e0 + e1 + e2);
        s_tc[0] = e0 * inv; s_tc[1] = e1 * inv; s_tc[2] = e2 * inv;
        s_idx[0] = id0; s_idx[1] = id1; s_idx[2] = id2;
    }
    __syncthreads();
    {
        int i0 = s_idx[0], i1 = s_idx[1], i2 = s_idx[2];
        float c0 = s_tc[0], c1 = s_tc[1], c2 = s_tc[2];
        const float* vb = vsrc + (size_t)b * SLC;
        for (int i = t; i < SLC; i += 512) {
            int l = i >> 7, d = i & 127;
            int p0 = l + i0; if (p0 >= Lz) p0 -= Lz;
            int p1 = l + i1; if (p1 >= Lz) p1 -= Lz;
            int p2 = l + i2; if (p2 >= Lz) p2 -= Lz;
            ag[i] = c0 * vb[p0 * Fz + d] + c1 * vb[p1 * Fz + d] + c2 * vb[p2 * Fz + d];
        }
    }
    __syncthreads();
    projH(outh, ag, Ws, bp, half);
    __syncthreads();
    float* dst = dstG + (size_t)b * SLC;
    for (int i = t; i < Lz * 64; i += 512) {
        int l = i >> 6, d = i & 63;
        dst[l * Fz + half * 64 + d] = outh[i];
    }
}

// ================= B kernel (1 or 2 ops, 128 blocks each) =========================
__global__ void __launch_bounds__(512) k_B(
        const float* m0, const float* v0, const float* W0, const float* b0, float* d0,
        const float* m1, const float* v1, const float* W1, const float* b1, float* d1) {
    extern __shared__ float sm[];
    float* ms   = sm;                  // 1600
    float* ag   = sm + 1600;           // 3200
    float* outh = sm + 4800;           // 1600
    float* Ws   = sm + 6400;           // 8448
    const int idx = blockIdx.x;
    const int op = idx >> 7, b = (idx & 127) >> 1, half = idx & 1;
    const float* mh = op ? m1 : m0;
    const float* vs = op ? v1 : v0;
    const float* Wp = op ? W1 : W0;
    const float* bp = op ? b1 : b0;
    float* dst = op ? d1 : d0;
    doB(mh, vs, Wp, bp, dst, ms, ag, outh, Ws, b, half);
}

// ================= final: POI (tf32 WMMA, fused exp-gather) + CAT =================
__global__ void __launch_bounds__(256) k_final(
        const float* __restrict__ outp, const float* __restrict__ outcp,
        const int* __restrict__ poi,  const float* __restrict__ Dm,
        const float* __restrict__ ce, const float* __restrict__ vw,
        const float* __restrict__ vbp, float* __restrict__ dst_poi,
        float* __restrict__ dst_cat) {
    extern __shared__ float sm[];
    const int bid = blockIdx.x, t = threadIdx.x;

    if (bid < 1280) {
        float* a_s = sm;
        float* S   = sm;
        __shared__ int   rows_s[50];
        __shared__ float vws[Lz];
        int wid = t >> 5;
        int ptile = bid % 40, b0 = (bid / 40) * 2;

        for (int i = t; i < 64 * 128; i += 256) {
            int r = i >> 7, d = i & 127;
            int l = r & 31, bb = b0 + (r >> 5);
            float v = 0.f;
            if (l < Lz) v = wmma::__float_to_tf32(outp[((bb * Lz) + l) * Fz + d]);
            a_s[i] = v;
        }
        if (t < 50) rows_s[t] = poi[(b0 + t / Lz) * Lz + (t % Lz)];
        if (t < Lz) vws[t] = vw[t];
        __syncthreads();

        wmma::fragment<wmma::matrix_a, 16, 16, 8, wmma::precision::tf32, wmma::row_major> fa;
        wmma::fragment<wmma::matrix_b, 16, 16, 8, wmma::precision::tf32, wmma::col_major> fb0, fb1;
        wmma::fragment<wmma::accumulator, 16, 16, 8, float> facc[4][2];
        #pragma unroll
        for (int m = 0; m < 4; m++) { wmma::fill_fragment(facc[m][0], 0.f); wmma::fill_fragment(facc[m][1], 0.f); }

        const float* peB = g_pe + (size_t)(ptile * 256) * Fz;
        for (int k = 0; k < 128; k += 8) {
            wmma::load_matrix_sync(fb0, peB + (size_t)((wid * 2 + 0) * 16) * Fz + k, Fz);
            wmma::load_matrix_sync(fb1, peB + (size_t)((wid * 2 + 1) * 16) * Fz + k, Fz);
            #pragma unroll
            for (int m = 0; m < 4; m++) {
                wmma::load_matrix_sync(fa, a_s + (m * 16) * Fz + k, Fz);
                wmma::mma_sync(facc[m][0], fa, fb0, facc[m][0]);
                wmma::mma_sync(facc[m][1], fa, fb1, facc[m][1]);
            }
        }
        __syncthreads();
        #pragma unroll
        for (int m = 0; m < 4; m++) {
            wmma::store_matrix_sync(S + (m * 16) * 264 + (wid * 2 + 0) * 16, facc[m][0], 264, wmma::mem_row_major);
            wmma::store_matrix_sync(S + (m * 16) * 264 + (wid * 2 + 1) * 16, facc[m][1], 264, wmma::mem_row_major);
        }
        __syncthreads();

        int p = ptile * 256 + t;
        if (p < Pz) {
            float neginv = -1.f / (__uint_as_float(g_maxbits) - __uint_as_float(g_minbits));
            float bias = vbp[0];
            #pragma unroll
            for (int bb = 0; bb < 2; bb++) {
                float r = 0.f;
                #pragma unroll
                for (int l = 0; l < Lz; l++) {
                    float s = S[(bb * 32 + l) * 264 + t];
                    float d = Dm[(size_t)rows_s[bb * Lz + l] * Pz + p];
                    r += s * __expf(d * neginv) * vws[l];
                }
                dst_poi[(size_t)(b0 + bb) * Pz + p] = r + bias;
            }
        }
    } else {
        int b = bid - 1280;
        float* y = sm;   // 128
        if (t < Fz) {
            float s = 0.f;
            for (int l = 0; l < Lz; l++) s += __ldg(&vw[l]) * outcp[(size_t)b * SLC + l * Fz + t];
            y[t] = s;
        }
        __syncthreads();
        int w = t >> 5, lane = t & 31;
        float bias = __ldg(vbp);
        const float4* Y4 = (const float4*)y;
        float4 yv = Y4[lane];
        for (int c = w; c < Cz; c += 8) {
            const float4* C4 = (const float4*)(ce + (size_t)c * Fz);
            float4 cv = __ldg(&C4[lane]);
            float s = cv.x * yv.x + cv.y * yv.y + cv.z * yv.z + cv.w * yv.w;
            #pragma unroll
            for (int off = 16; off > 0; off >>= 1) s += __shfl_down_sync(0xffffffffu, s, off);
            if (lane == 0) dst_cat[b * Cz + c] = s + bias;
        }
    }
}

// ---------------- host driver ----------------------------------------------------
extern "C" void kernel_launch(void* const* d_in, const int* in_sizes, int n_in,
                              void* d_out, int out_size) {
    const int*   user = (const int*)d_in[0];
    const int*   poi  = (const int*)d_in[1];
    const int*   cat  = (const int*)d_in[2];
    const int*   tod  = (const int*)d_in[5];
    const int*   dow  = (const int*)d_in[6];
    const float* ue   = (const float*)d_in[8];
    const float* pe   = (const float*)d_in[9];
    const float* ce   = (const float*)d_in[10];
    const float* te   = (const float*)d_in[11];
    const float* de   = (const float*)d_in[12];
    const float* uec  = (const float*)d_in[13];
    const float* tec  = (const float*)d_in[14];
    const float* dec  = (const float*)d_in[15];
    const float* W    = (const float*)d_in[16];
    const float* Bvv  = (const float*)d_in[17];
    const float* vw   = (const float*)d_in[18];
    const float* vb   = (const float*)d_in[19];
    const float* Dm   = (const float*)d_in[20];
    float* out = (float*)d_out;

    const int ASM = (2 * SLC + 3 * Lz * 64 + WTS) * 4;    // 78592 B
    const int BSM = (Bz * Lz + SLC + Lz * 64 + WTS) * 4;  // 59392 B
    const int FSM = 64 * 264 * 4;                          // 67584 B

    static int attr_done = 0;
    if (!attr_done) {
        cudaFuncSetAttribute(k_A,     cudaFuncAttributeMaxDynamicSharedMemorySize, ASM);
        cudaFuncSetAttribute(k_B,     cudaFuncAttributeMaxDynamicSharedMemorySize, BSM);
        cudaFuncSetAttribute(k_final, cudaFuncAttributeMaxDynamicSharedMemorySize, FSM);
        attr_done = 1;
    }

    float* stp;  cudaGetSymbolAddress((void**)&stp, g_st);
    float* vp;   cudaGetSymbolAddress((void**)&vp,  g_v8);
    float* mp;   cudaGetSymbolAddress((void**)&mp,  g_meanH);
    #define ST(i)  (stp + (size_t)(i) * BL * Fz)
    #define VV(i)  (vp  + (size_t)(i) * BL * Fz)
    #define MM(i)  (mp  + (size_t)(i) * 2 * Bz * Lz)
    #define WQKV(c) (W   + (size_t)(c) * 4 * Fz * Fz)
    #define WPRJ(c) (W   + (size_t)(c) * 4 * Fz * Fz + 3 * Fz * Fz)
    #define BQKV(c) (Bvv + (size_t)(c) * 4 * Fz)
    #define BPRJ(c) (Bvv + (size_t)(c) * 4 * Fz + 3 * Fz)

    k_pre<<<2912, 256>>>(user, poi, cat, tod, dow, ue, pe, ce, te, de, uec, tec, dec, Dm);

    // c0: AC(x,x) ; c1: AC(xc,xc)
    k_A<<<256, 512, ASM>>>(ST(0), ST(0), WQKV(0), BQKV(0), VV(0), MM(0),
                           ST(1), ST(1), WQKV(1), BQKV(1), VV(1), MM(1));
    k_B<<<256, 512, BSM>>>(MM(0), VV(0), WPRJ(0), BPRJ(0), ST(2),
                           MM(1), VV(1), WPRJ(1), BPRJ(1), ST(3));
    // c2: AC(out1, outc1)
    k_A<<<128, 512, ASM>>>(ST(2), ST(3), WQKV(2), BQKV(2), VV(2), MM(2),
                           nullptr, nullptr, nullptr, nullptr, nullptr, nullptr);
    k_B<<<128, 512, BSM>>>(MM(2), VV(2), WPRJ(2), BPRJ(2), ST(4),
                           nullptr, nullptr, nullptr, nullptr, nullptr);
    // c3: AC(outc1, out2) ; c4 (=L2 c0): AC(out2, out2)
    k_A<<<256, 512, ASM>>>(ST(3), ST(4), WQKV(3), BQKV(3), VV(3), MM(3),
                           ST(4), ST(4), WQKV(4), BQKV(4), VV(4), MM(4));
    k_B<<<256, 512, BSM>>>(MM(3), VV(3), WPRJ(3), BPRJ(3), ST(5),
                           MM(4), VV(4), WPRJ(4), BPRJ(4), ST(6));
    // c5: AC(outc2, outc2)
    k_A<<<128, 512, ASM>>>(ST(5), ST(5), WQKV(5), BQKV(5), VV(5), MM(5),
                           nullptr, nullptr, nullptr, nullptr, nullptr, nullptr);
    k_B<<<128, 512, BSM>>>(MM(5), VV(5), WPRJ(5), BPRJ(5), ST(7),
                           nullptr, nullptr, nullptr, nullptr, nullptr);
    // c6: AC(out3, outc3)
    k_A<<<128, 512, ASM>>>(ST(6), ST(7), WQKV(6), BQKV(6), VV(6), MM(6),
                           nullptr, nullptr, nullptr, nullptr, nullptr, nullptr);
    k_B<<<128, 512, BSM>>>(MM(6), VV(6), WPRJ(6), BPRJ(6), ST(8),
                           nullptr, nullptr, nullptr, nullptr, nullptr);
    // c7: AC(outc3, out4)
    k_A<<<128, 512, ASM>>>(ST(7), ST(8), WQKV(7), BQKV(7), VV(7), MM(7),
                           nullptr, nullptr, nullptr, nullptr, nullptr, nullptr);
    k_B<<<128, 512, BSM>>>(MM(7), VV(7), WPRJ(7), BPRJ(7), ST(9),
                           nullptr, nullptr, nullptr, nullptr, nullptr);

    // final: POI (1280 blocks) + CAT (64 blocks)
    k_final<<<1344, 256, FSM>>>(ST(8), ST(9), poi, Dm, ce, vw, vb,
                                out, out + (size_t)Bz * Pz);
}